// round 6
// baseline (speedup 1.0000x reference)
#include <cuda_runtime.h>
#include <cuda_bf16.h>
#include <float.h>
#include <math.h>

#define NN     50000
#define EEDGE  800000
#define ETOT   (EEDGE + NN)

// ---------------- device scratch ----------------
__device__ float g_bufA[(size_t)NN * 256];
__device__ float g_bufB[(size_t)NN * 256];
__device__ float g_es[(size_t)NN * 4];
__device__ float g_ed[(size_t)NN * 4];
__device__ int   g_cnt[NN];
__device__ int   g_cursor[NN];
__device__ int   g_row_ptr[NN + 1];
__device__ int   g_col_src[ETOT];
__device__ int   g_part[64];

// ---------------- tf32 helpers ----------------
__device__ __forceinline__ unsigned tf32h(float x) {
    unsigned u;
    asm("cvt.rna.tf32.f32 %0, %1;" : "=r"(u) : "f"(x));
    return u;
}
__device__ __forceinline__ void mma_tf32(float* c, const unsigned* a, const unsigned* b) {
    asm volatile("mma.sync.aligned.m16n8k8.row.col.f32.tf32.tf32.f32 "
        "{%0,%1,%2,%3}, {%4,%5,%6,%7}, {%8,%9}, {%0,%1,%2,%3};"
        : "+f"(c[0]), "+f"(c[1]), "+f"(c[2]), "+f"(c[3])
        : "r"(a[0]), "r"(a[1]), "r"(a[2]), "r"(a[3]), "r"(b[0]), "r"(b[1]));
}

// ---------------- CSR construction ----------------
__global__ void k_zero_int(int* __restrict__ p, int n) {
    int i = blockIdx.x * blockDim.x + threadIdx.x;
    if (i < n) p[i] = 0;
}

__global__ void k_hist(const int* __restrict__ ei, int E, int n, int* __restrict__ cnt) {
    int i = blockIdx.x * blockDim.x + threadIdx.x;
    int tot = E + n;
    if (i < tot) {
        int d = (i < E) ? ei[E + i] : (i - E);
        atomicAdd(&cnt[d], 1);
    }
}

__global__ void k_scan1(const int* __restrict__ cnt, int n,
                        int* __restrict__ incl, int* __restrict__ part) {
    __shared__ int sh[1024];
    const int t = threadIdx.x;
    const int i = blockIdx.x * 1024 + t;
    int v = (i < n) ? cnt[i] : 0;
    sh[t] = v;
    __syncthreads();
    #pragma unroll
    for (int o = 1; o < 1024; o <<= 1) {
        int add = (t >= o) ? sh[t - o] : 0;
        __syncthreads();
        sh[t] += add;
        __syncthreads();
    }
    if (i < n) incl[i] = sh[t];
    if (t == 1023) part[blockIdx.x] = sh[1023];
}

__global__ void k_scan23(const int* __restrict__ cnt, int n,
                         int* __restrict__ row_ptr, int* __restrict__ cursor,
                         const int* __restrict__ part) {
    __shared__ int soff;
    const int t = threadIdx.x;
    if (t < 32) {
        int s = 0;
        for (int i = t; i < (int)blockIdx.x; i += 32) s += part[i];
        #pragma unroll
        for (int o = 16; o; o >>= 1) s += __shfl_xor_sync(0xffffffffu, s, o);
        if (t == 0) soff = s;
    }
    __syncthreads();
    const int i = blockIdx.x * 1024 + t;
    if (i < n) {
        int incl = row_ptr[i];
        int c = cnt[i];
        int exc = incl - c + soff;
        row_ptr[i] = exc;
        cursor[i] = exc;
        if (i == n - 1) row_ptr[n] = exc + c;
    }
}

__global__ void k_scatter(const int* __restrict__ ei, int E, int n,
                          int* __restrict__ cursor, int* __restrict__ col_src) {
    int i = blockIdx.x * blockDim.x + threadIdx.x;
    int tot = E + n;
    if (i < tot) {
        int s = (i < E) ? ei[i]     : (i - E);
        int d = (i < E) ? ei[E + i] : (i - E);
        int pos = atomicAdd(&cursor[d], 1);
        col_src[pos] = s;
    }
}

// ---------------- GEMM, K=16 (layer 1) ----------------
__global__ void k_gemm16(const float* __restrict__ X, const float* __restrict__ W,
                         float* __restrict__ O, int nrows) {
    __shared__ float Wsh[16 * 256];
    __shared__ float Xsh[16 * 16];
    const int t = threadIdx.x;
    for (int i = t; i < 16 * 256; i += 256) Wsh[i] = W[i];
    const int r0 = blockIdx.x * 16;
    {
        int r = t >> 4, c = t & 15;
        int rr = r0 + r; if (rr >= nrows) rr = nrows - 1;
        Xsh[t] = X[(size_t)rr * 16 + c];
    }
    __syncthreads();
    float acc[16];
    #pragma unroll
    for (int r = 0; r < 16; r++) acc[r] = 0.f;
    #pragma unroll
    for (int k = 0; k < 16; k++) {
        float w = Wsh[k * 256 + t];
        #pragma unroll
        for (int r = 0; r < 16; r++) acc[r] = fmaf(Xsh[r * 16 + k], w, acc[r]);
    }
    #pragma unroll
    for (int r = 0; r < 16; r++) {
        int rr = r0 + r;
        if (rr < nrows) O[(size_t)rr * 256 + t] = acc[r];
    }
}

// ---------------- tf32x3 tensor GEMM + fused attention dots epilogue ----------------
template <int NT, int H>
__global__ void __launch_bounds__(256)
k_gemm_tf32(const float* __restrict__ X, const float* __restrict__ W,
            float* __restrict__ O, int nrows,
            const float* __restrict__ As, const float* __restrict__ Ad,
            float* __restrict__ esv, float* __restrict__ edv) {
    __shared__ __align__(16) float Xs[128][36];
    __shared__ __align__(16) float Ws[32][72];
    __shared__ float esr[128], edr[128];

    const int t = threadIdx.x;
    const int lane = t & 31;
    const int w = t >> 5;
    const int warp_m = w >> 1;
    const int warp_n = w & 1;
    const int lr = lane >> 2;
    const int lc = lane & 3;
    const int r0 = blockIdx.x * 128;
    const int n0 = blockIdx.y * 64;
    const int head = blockIdx.y;

    float acc[2][4][4];
    #pragma unroll
    for (int mt = 0; mt < 2; mt++)
        #pragma unroll
        for (int nt = 0; nt < 4; nt++)
            #pragma unroll
            for (int i = 0; i < 4; i++) acc[mt][nt][i] = 0.f;

    for (int k0 = 0; k0 < 256; k0 += 32) {
        __syncthreads();
        #pragma unroll
        for (int j = 0; j < 4; j++) {
            int idx = t + j * 256;
            int row = idx >> 3, c4 = idx & 7;
            int rr = r0 + row; if (rr >= nrows) rr = nrows - 1;
            *reinterpret_cast<float4*>(&Xs[row][c4 * 4]) =
                *reinterpret_cast<const float4*>(X + (size_t)rr * 256 + k0 + c4 * 4);
        }
        #pragma unroll
        for (int j = 0; j < 2; j++) {
            int idx = t + j * 256;
            int row = idx >> 4, c4 = idx & 15;
            *reinterpret_cast<float4*>(&Ws[row][c4 * 4]) =
                *reinterpret_cast<const float4*>(W + (size_t)(k0 + row) * NT + n0 + c4 * 4);
        }
        __syncthreads();

        #pragma unroll
        for (int ks = 0; ks < 4; ks++) {
            const int kk = ks * 8;
            unsigned bhi[4][2], blo[4][2];
            #pragma unroll
            for (int nt = 0; nt < 4; nt++) {
                int cb = warp_n * 32 + nt * 8 + lr;
                float b0 = Ws[kk + lc][cb];
                float b1 = Ws[kk + lc + 4][cb];
                bhi[nt][0] = tf32h(b0);
                bhi[nt][1] = tf32h(b1);
                blo[nt][0] = tf32h(b0 - __uint_as_float(bhi[nt][0]));
                blo[nt][1] = tf32h(b1 - __uint_as_float(bhi[nt][1]));
            }
            #pragma unroll
            for (int mt = 0; mt < 2; mt++) {
                int ar = warp_m * 32 + mt * 16 + lr;
                float a0 = Xs[ar][kk + lc];
                float a1 = Xs[ar + 8][kk + lc];
                float a2 = Xs[ar][kk + lc + 4];
                float a3 = Xs[ar + 8][kk + lc + 4];
                unsigned ah[4] = {tf32h(a0), tf32h(a1), tf32h(a2), tf32h(a3)};
                unsigned al[4] = {tf32h(a0 - __uint_as_float(ah[0])),
                                  tf32h(a1 - __uint_as_float(ah[1])),
                                  tf32h(a2 - __uint_as_float(ah[2])),
                                  tf32h(a3 - __uint_as_float(ah[3]))};
                #pragma unroll
                for (int nt = 0; nt < 4; nt++) {
                    mma_tf32(acc[mt][nt], al, bhi[nt]);
                    mma_tf32(acc[mt][nt], ah, blo[nt]);
                    mma_tf32(acc[mt][nt], ah, bhi[nt]);
                }
            }
        }
    }

    #pragma unroll
    for (int mt = 0; mt < 2; mt++) {
        #pragma unroll
        for (int nt = 0; nt < 4; nt++) {
            int row = r0 + warp_m * 32 + mt * 16 + lr;
            int colg = n0 + warp_n * 32 + nt * 8 + lc * 2;
            if (row < nrows) {
                float2 v0 = make_float2(acc[mt][nt][0], acc[mt][nt][1]);
                *reinterpret_cast<float2*>(O + (size_t)row * NT + colg) = v0;
            }
            if (row + 8 < nrows) {
                float2 v1 = make_float2(acc[mt][nt][2], acc[mt][nt][3]);
                *reinterpret_cast<float2*>(O + (size_t)(row + 8) * NT + colg) = v1;
            }
        }
    }

    // ---- fused dots epilogue ----
    for (int i = t; i < 128; i += 256) { esr[i] = 0.f; edr[i] = 0.f; }
    __syncthreads();
    float pes[4] = {0, 0, 0, 0}, ped[4] = {0, 0, 0, 0};
    #pragma unroll
    for (int nt = 0; nt < 4; nt++) {
        int cb = warp_n * 32 + nt * 8 + lc * 2;
        float as0 = As[head * 64 + cb], as1 = As[head * 64 + cb + 1];
        float ad0 = Ad[head * 64 + cb], ad1 = Ad[head * 64 + cb + 1];
        #pragma unroll
        for (int mt = 0; mt < 2; mt++) {
            pes[mt * 2 + 0] += acc[mt][nt][0] * as0 + acc[mt][nt][1] * as1;
            pes[mt * 2 + 1] += acc[mt][nt][2] * as0 + acc[mt][nt][3] * as1;
            ped[mt * 2 + 0] += acc[mt][nt][0] * ad0 + acc[mt][nt][1] * ad1;
            ped[mt * 2 + 1] += acc[mt][nt][2] * ad0 + acc[mt][nt][3] * ad1;
        }
    }
    #pragma unroll
    for (int j = 0; j < 4; j++) {
        #pragma unroll
        for (int o = 1; o <= 2; o <<= 1) {
            pes[j] += __shfl_xor_sync(0xffffffffu, pes[j], o);
            ped[j] += __shfl_xor_sync(0xffffffffu, ped[j], o);
        }
    }
    if (lc == 0) {
        #pragma unroll
        for (int j = 0; j < 4; j++) {
            int rl = warp_m * 32 + (j >> 1) * 16 + lr + (j & 1) * 8;
            atomicAdd(&esr[rl], pes[j]);
            atomicAdd(&edr[rl], ped[j]);
        }
    }
    __syncthreads();
    if (t < 128) {
        int row = r0 + t;
        if (row < nrows) {
            esv[(size_t)row * H + head] = esr[t];
            edv[(size_t)row * H + head] = edr[t];
        }
    }
}

// ---------------- attention dot products (layer 1 only) ----------------
template <int H>
__global__ void k_dots(const float* __restrict__ Hm, const float* __restrict__ As,
                       const float* __restrict__ Ad, float* __restrict__ es,
                       float* __restrict__ ed) {
    const int node = blockIdx.x;
    const int w = threadIdx.x >> 5;
    const int l = threadIdx.x & 31;
    const float* hp = Hm + (size_t)node * (H * 64) + w * 64;
    float s1 = fmaf(hp[l], As[w * 64 + l], hp[l + 32] * As[w * 64 + l + 32]);
    float s2 = fmaf(hp[l], Ad[w * 64 + l], hp[l + 32] * Ad[w * 64 + l + 32]);
    #pragma unroll
    for (int o = 16; o; o >>= 1) {
        s1 += __shfl_xor_sync(0xffffffffu, s1, o);
        s2 += __shfl_xor_sync(0xffffffffu, s2, o);
    }
    if (l == 0) { es[node * H + w] = s1; ed[node * H + w] = s2; }
}

// ---------------- fused softmax + aggregation (persistent) ----------------
template <int H, bool ELU>
__global__ void __launch_bounds__(H * 64)
k_fused(const float* __restrict__ Hm, const float* __restrict__ es,
        const float* __restrict__ ed, const int* __restrict__ row_ptr,
        const int* __restrict__ col, const float* __restrict__ bias,
        float* __restrict__ out, int n) {
    constexpr int F = H * 64;
    constexpr int CAP = 512;
    const int t = threadIdx.x;
    const int head = t >> 6;
    const int w = t >> 5;
    const int l = t & 31;

    __shared__ int   scol[CAP];
    __shared__ float se[H][CAP];
    __shared__ float sinv[H];
    __shared__ float m_sh[H], den_sh[H], scale_sh[H], cmax[H], csum[H];

    const float bi = bias[t];

    for (int node = blockIdx.x; node < n; node += gridDim.x) {
        const int beg = row_ptr[node];
        const int end = row_ptr[node + 1];
        const int deg = end - beg;

        if (deg == 0) {
            float r = bi;
            if (ELU) r = (r > 0.f) ? r : expm1f(r);
            out[(size_t)node * F + t] = r;
            continue;
        }

        if (deg <= CAP) {
            for (int i = t; i < deg; i += F) scol[i] = col[beg + i];
            __syncthreads();

            if (w < H) {
                const float edl = ed[node * H + w];
                float mm = -FLT_MAX;
                for (int c = l; c < deg; c += 32) {
                    float e = es[scol[c] * H + w] + edl;
                    e = (e > 0.f) ? e : 0.2f * e;
                    se[w][c] = e;
                    mm = fmaxf(mm, e);
                }
                #pragma unroll
                for (int o = 16; o; o >>= 1) mm = fmaxf(mm, __shfl_xor_sync(0xffffffffu, mm, o));
                float ss = 0.f;
                for (int c = l; c < deg; c += 32) {
                    float ex = __expf(se[w][c] - mm);
                    se[w][c] = ex;
                    ss += ex;
                }
                #pragma unroll
                for (int o = 16; o; o >>= 1) ss += __shfl_xor_sync(0xffffffffu, ss, o);
                if (l == 0) sinv[w] = 1.0f / ss;
            }
            __syncthreads();

            float a0 = 0.f, a1 = 0.f, a2 = 0.f, a3 = 0.f;
            float a4 = 0.f, a5 = 0.f, a6 = 0.f, a7 = 0.f;
            int c = 0;
            for (; c + 8 <= deg; c += 8) {
                int s0 = scol[c],     s1 = scol[c + 1], s2 = scol[c + 2], s3 = scol[c + 3];
                int s4 = scol[c + 4], s5 = scol[c + 5], s6 = scol[c + 6], s7 = scol[c + 7];
                float w0 = se[head][c],     w1 = se[head][c + 1];
                float w2 = se[head][c + 2], w3 = se[head][c + 3];
                float w4 = se[head][c + 4], w5 = se[head][c + 5];
                float w6 = se[head][c + 6], w7 = se[head][c + 7];
                a0 = fmaf(Hm[(size_t)s0 * F + t], w0, a0);
                a1 = fmaf(Hm[(size_t)s1 * F + t], w1, a1);
                a2 = fmaf(Hm[(size_t)s2 * F + t], w2, a2);
                a3 = fmaf(Hm[(size_t)s3 * F + t], w3, a3);
                a4 = fmaf(Hm[(size_t)s4 * F + t], w4, a4);
                a5 = fmaf(Hm[(size_t)s5 * F + t], w5, a5);
                a6 = fmaf(Hm[(size_t)s6 * F + t], w6, a6);
                a7 = fmaf(Hm[(size_t)s7 * F + t], w7, a7);
            }
            for (; c < deg; c++)
                a0 = fmaf(Hm[(size_t)scol[c] * F + t], se[head][c], a0);

            float res = ((a0 + a1) + (a2 + a3)) + ((a4 + a5) + (a6 + a7));
            res = res * sinv[head] + bi;
            if (ELU) res = (res > 0.f) ? res : expm1f(res);
            out[(size_t)node * F + t] = res;
            __syncthreads();
        } else {
            if (t < H) { m_sh[t] = -FLT_MAX; den_sh[t] = 0.f; }
            float acc = 0.f;
            const float edl = (w < H) ? ed[node * H + w] : 0.f;
            __syncthreads();
            for (int ch = beg; ch < end; ch += CAP) {
                const int len = min(CAP, end - ch);
                for (int i = t; i < len; i += F) scol[i] = col[ch + i];
                __syncthreads();
                if (w < H) {
                    float mm = -FLT_MAX;
                    for (int c = l; c < len; c += 32) {
                        float e = es[scol[c] * H + w] + edl;
                        e = (e > 0.f) ? e : 0.2f * e;
                        se[w][c] = e;
                        mm = fmaxf(mm, e);
                    }
                    #pragma unroll
                    for (int o = 16; o; o >>= 1) mm = fmaxf(mm, __shfl_xor_sync(0xffffffffu, mm, o));
                    if (l == 0) cmax[w] = mm;
                }
                __syncthreads();
                if (t < H) {
                    float nm = fmaxf(m_sh[t], cmax[t]);
                    float sc = __expf(m_sh[t] - nm);
                    scale_sh[t] = sc;
                    m_sh[t] = nm;
                    den_sh[t] *= sc;
                }
                __syncthreads();
                if (w < H) {
                    float ss = 0.f;
                    const float nm = m_sh[w];
                    for (int c = l; c < len; c += 32) {
                        float ex = __expf(se[w][c] - nm);
                        se[w][c] = ex;
                        ss += ex;
                    }
                    #pragma unroll
                    for (int o = 16; o; o >>= 1) ss += __shfl_xor_sync(0xffffffffu, ss, o);
                    if (l == 0) csum[w] = ss;
                }
                acc *= scale_sh[head];
                __syncthreads();
                if (t < H) den_sh[t] += csum[t];
                for (int c = 0; c < len; c++)
                    acc = fmaf(Hm[(size_t)scol[c] * F + t], se[head][c], acc);
                __syncthreads();
            }
            float res = acc / den_sh[head] + bi;
            if (ELU) res = (res > 0.f) ? res : expm1f(res);
            out[(size_t)node * F + t] = res;
            __syncthreads();
        }
    }
}

// ---------------- graph embedding mean ----------------
__global__ void k_zero_f(float* __restrict__ p, int n) {
    int i = blockIdx.x * blockDim.x + threadIdx.x;
    if (i < n) p[i] = 0.f;
}

__global__ void k_mean(const float* __restrict__ node_emb, float* __restrict__ out, int n) {
    const int t = threadIdx.x;  // 64
    float a = 0.f;
    for (int r = blockIdx.x; r < n; r += gridDim.x)
        a += node_emb[(size_t)r * 64 + t];
    atomicAdd(&out[t], a * (1.0f / (float)n));
}

// ---------------- launch ----------------
// MEASUREMENT ROUND: identical to round 5 except each k_fused launch is issued
// 3x (idempotent). Delta vs 858.6us = 2 * (t_fused1 + t_fused2 + t_fused3).
extern "C" void kernel_launch(void* const* d_in, const int* in_sizes, int n_in,
                              void* d_out, int out_size) {
    const float* x   = (const float*)d_in[0];
    const int*   ei  = (const int*)d_in[1];
    const float* W1  = (const float*)d_in[2];
    const float* a1s = (const float*)d_in[3];
    const float* a1d = (const float*)d_in[4];
    const float* b1  = (const float*)d_in[5];
    const float* W2  = (const float*)d_in[6];
    const float* a2s = (const float*)d_in[7];
    const float* a2d = (const float*)d_in[8];
    const float* b2  = (const float*)d_in[9];
    const float* W3  = (const float*)d_in[10];
    const float* a3s = (const float*)d_in[11];
    const float* a3d = (const float*)d_in[12];
    const float* b3  = (const float*)d_in[13];
    float* out = (float*)d_out;

    const int n = in_sizes[0] / 16;   // 50000
    const int E = in_sizes[1] / 2;    // 800000
    const int tot = E + n;
    const int B = (n + 1023) / 1024;

    float *bufA, *bufB, *es, *ed;
    int *cnt, *cursor, *row_ptr, *col, *part;
    cudaGetSymbolAddress((void**)&bufA, g_bufA);
    cudaGetSymbolAddress((void**)&bufB, g_bufB);
    cudaGetSymbolAddress((void**)&es, g_es);
    cudaGetSymbolAddress((void**)&ed, g_ed);
    cudaGetSymbolAddress((void**)&cnt, g_cnt);
    cudaGetSymbolAddress((void**)&cursor, g_cursor);
    cudaGetSymbolAddress((void**)&row_ptr, g_row_ptr);
    cudaGetSymbolAddress((void**)&col, g_col_src);
    cudaGetSymbolAddress((void**)&part, g_part);

    // CSR by dst
    k_zero_int<<<(n + 255) / 256, 256>>>(cnt, n);
    k_hist<<<(tot + 255) / 256, 256>>>(ei, E, n, cnt);
    k_scan1<<<B, 1024>>>(cnt, n, row_ptr, part);
    k_scan23<<<B, 1024>>>(cnt, n, row_ptr, cursor, part);
    k_scatter<<<(tot + 255) / 256, 256>>>(ei, E, n, cursor, col);

    // layer 1
    k_gemm16<<<(n + 15) / 16, 256>>>(x, W1, bufA, n);
    k_dots<4><<<n, 128>>>(bufA, a1s, a1d, es, ed);
    k_fused<4, true><<<1184, 256>>>(bufA, es, ed, row_ptr, col, b1, bufB, n);
    k_fused<4, true><<<1184, 256>>>(bufA, es, ed, row_ptr, col, b1, bufB, n);  // probe dup
    k_fused<4, true><<<1184, 256>>>(bufA, es, ed, row_ptr, col, b1, bufB, n);  // probe dup

    // layer 2 (tf32x3 GEMM + fused dots)
    {
        dim3 g((n + 127) / 128, 4);
        k_gemm_tf32<256, 4><<<g, 256>>>(bufB, W2, bufA, n, a2s, a2d, es, ed);
    }
    k_fused<4, true><<<1184, 256>>>(bufA, es, ed, row_ptr, col, b2, bufB, n);
    k_fused<4, true><<<1184, 256>>>(bufA, es, ed, row_ptr, col, b2, bufB, n);  // probe dup
    k_fused<4, true><<<1184, 256>>>(bufA, es, ed, row_ptr, col, b2, bufB, n);  // probe dup

    // layer 3 (tf32x3 GEMM + fused dots, N=64)
    {
        dim3 g((n + 127) / 128, 1);
        k_gemm_tf32<64, 1><<<g, 256>>>(bufB, W3, bufA, n, a3s, a3d, es, ed);
    }
    k_fused<1, false><<<2368, 64>>>(bufA, es, ed, row_ptr, col, b3, out, n);
    k_fused<1, false><<<2368, 64>>>(bufA, es, ed, row_ptr, col, b3, out, n);   // probe dup
    k_fused<1, false><<<2368, 64>>>(bufA, es, ed, row_ptr, col, b3, out, n);   // probe dup

    // graph embedding
    k_zero_f<<<1, 64>>>(out + (size_t)n * 64, 64);
    k_mean<<<256, 64>>>(out, out + (size_t)n * 64, n);
}

// round 7
// speedup vs baseline: 3.6561x; 3.6561x over previous
#include <cuda_runtime.h>
#include <cuda_bf16.h>
#include <float.h>
#include <math.h>

#define NN     50000
#define EEDGE  800000
#define ETOT   (EEDGE + NN)

// ---------------- device scratch ----------------
__device__ float g_bufA[(size_t)NN * 256];
__device__ float g_bufB[(size_t)NN * 256];
__device__ float g_es[(size_t)NN * 4];
__device__ float g_ed[(size_t)NN * 4];
__device__ int   g_cnt[NN];
__device__ int   g_cursor[NN];
__device__ int   g_row_ptr[NN + 1];
__device__ int   g_col_src[ETOT];
__device__ int   g_part[64];

// ---------------- tf32 helpers ----------------
__device__ __forceinline__ unsigned tf32h(float x) {
    unsigned u;
    asm("cvt.rna.tf32.f32 %0, %1;" : "=r"(u) : "f"(x));
    return u;
}
__device__ __forceinline__ void mma_tf32(float* c, const unsigned* a, const unsigned* b) {
    asm volatile("mma.sync.aligned.m16n8k8.row.col.f32.tf32.tf32.f32 "
        "{%0,%1,%2,%3}, {%4,%5,%6,%7}, {%8,%9}, {%0,%1,%2,%3};"
        : "+f"(c[0]), "+f"(c[1]), "+f"(c[2]), "+f"(c[3])
        : "r"(a[0]), "r"(a[1]), "r"(a[2]), "r"(a[3]), "r"(b[0]), "r"(b[1]));
}

// ---------------- CSR construction ----------------
__global__ void k_zero_int(int* __restrict__ p, int n) {
    int i = blockIdx.x * blockDim.x + threadIdx.x;
    if (i < n) p[i] = 0;
}

__global__ void k_hist(const int* __restrict__ ei, int E, int n, int* __restrict__ cnt) {
    int i = blockIdx.x * blockDim.x + threadIdx.x;
    int tot = E + n;
    if (i < tot) {
        int d = (i < E) ? ei[E + i] : (i - E);
        atomicAdd(&cnt[d], 1);
    }
}

__global__ void k_scan1(const int* __restrict__ cnt, int n,
                        int* __restrict__ incl, int* __restrict__ part) {
    __shared__ int sh[1024];
    const int t = threadIdx.x;
    const int i = blockIdx.x * 1024 + t;
    int v = (i < n) ? cnt[i] : 0;
    sh[t] = v;
    __syncthreads();
    #pragma unroll
    for (int o = 1; o < 1024; o <<= 1) {
        int add = (t >= o) ? sh[t - o] : 0;
        __syncthreads();
        sh[t] += add;
        __syncthreads();
    }
    if (i < n) incl[i] = sh[t];
    if (t == 1023) part[blockIdx.x] = sh[1023];
}

__global__ void k_scan23(const int* __restrict__ cnt, int n,
                         int* __restrict__ row_ptr, int* __restrict__ cursor,
                         const int* __restrict__ part) {
    __shared__ int soff;
    const int t = threadIdx.x;
    if (t < 32) {
        int s = 0;
        for (int i = t; i < (int)blockIdx.x; i += 32) s += part[i];
        #pragma unroll
        for (int o = 16; o; o >>= 1) s += __shfl_xor_sync(0xffffffffu, s, o);
        if (t == 0) soff = s;
    }
    __syncthreads();
    const int i = blockIdx.x * 1024 + t;
    if (i < n) {
        int incl = row_ptr[i];
        int c = cnt[i];
        int exc = incl - c + soff;
        row_ptr[i] = exc;
        cursor[i] = exc;
        if (i == n - 1) row_ptr[n] = exc + c;
    }
}

__global__ void k_scatter(const int* __restrict__ ei, int E, int n,
                          int* __restrict__ cursor, int* __restrict__ col_src) {
    int i = blockIdx.x * blockDim.x + threadIdx.x;
    int tot = E + n;
    if (i < tot) {
        int s = (i < E) ? ei[i]     : (i - E);
        int d = (i < E) ? ei[E + i] : (i - E);
        int pos = atomicAdd(&cursor[d], 1);
        col_src[pos] = s;
    }
}

// ---------------- GEMM, K=16 (layer 1) ----------------
__global__ void k_gemm16(const float* __restrict__ X, const float* __restrict__ W,
                         float* __restrict__ O, int nrows) {
    __shared__ float Wsh[16 * 256];
    __shared__ float Xsh[16 * 16];
    const int t = threadIdx.x;
    for (int i = t; i < 16 * 256; i += 256) Wsh[i] = W[i];
    const int r0 = blockIdx.x * 16;
    {
        int r = t >> 4, c = t & 15;
        int rr = r0 + r; if (rr >= nrows) rr = nrows - 1;
        Xsh[t] = X[(size_t)rr * 16 + c];
    }
    __syncthreads();
    float acc[16];
    #pragma unroll
    for (int r = 0; r < 16; r++) acc[r] = 0.f;
    #pragma unroll
    for (int k = 0; k < 16; k++) {
        float w = Wsh[k * 256 + t];
        #pragma unroll
        for (int r = 0; r < 16; r++) acc[r] = fmaf(Xsh[r * 16 + k], w, acc[r]);
    }
    #pragma unroll
    for (int r = 0; r < 16; r++) {
        int rr = r0 + r;
        if (rr < nrows) O[(size_t)rr * 256 + t] = acc[r];
    }
}

// ---------------- tf32x3 tensor GEMM + fused attention dots epilogue ----------------
template <int NT, int H>
__global__ void __launch_bounds__(256)
k_gemm_tf32(const float* __restrict__ X, const float* __restrict__ W,
            float* __restrict__ O, int nrows,
            const float* __restrict__ As, const float* __restrict__ Ad,
            float* __restrict__ esv, float* __restrict__ edv) {
    __shared__ __align__(16) float Xs[128][36];
    __shared__ __align__(16) float Ws[32][72];
    __shared__ float esr[128], edr[128];

    const int t = threadIdx.x;
    const int lane = t & 31;
    const int w = t >> 5;
    const int warp_m = w >> 1;
    const int warp_n = w & 1;
    const int lr = lane >> 2;
    const int lc = lane & 3;
    const int r0 = blockIdx.x * 128;
    const int n0 = blockIdx.y * 64;
    const int head = blockIdx.y;

    float acc[2][4][4];
    #pragma unroll
    for (int mt = 0; mt < 2; mt++)
        #pragma unroll
        for (int nt = 0; nt < 4; nt++)
            #pragma unroll
            for (int i = 0; i < 4; i++) acc[mt][nt][i] = 0.f;

    for (int k0 = 0; k0 < 256; k0 += 32) {
        __syncthreads();
        #pragma unroll
        for (int j = 0; j < 4; j++) {
            int idx = t + j * 256;
            int row = idx >> 3, c4 = idx & 7;
            int rr = r0 + row; if (rr >= nrows) rr = nrows - 1;
            *reinterpret_cast<float4*>(&Xs[row][c4 * 4]) =
                *reinterpret_cast<const float4*>(X + (size_t)rr * 256 + k0 + c4 * 4);
        }
        #pragma unroll
        for (int j = 0; j < 2; j++) {
            int idx = t + j * 256;
            int row = idx >> 4, c4 = idx & 15;
            *reinterpret_cast<float4*>(&Ws[row][c4 * 4]) =
                *reinterpret_cast<const float4*>(W + (size_t)(k0 + row) * NT + n0 + c4 * 4);
        }
        __syncthreads();

        #pragma unroll
        for (int ks = 0; ks < 4; ks++) {
            const int kk = ks * 8;
            unsigned bhi[4][2], blo[4][2];
            #pragma unroll
            for (int nt = 0; nt < 4; nt++) {
                int cb = warp_n * 32 + nt * 8 + lr;
                float b0 = Ws[kk + lc][cb];
                float b1 = Ws[kk + lc + 4][cb];
                bhi[nt][0] = tf32h(b0);
                bhi[nt][1] = tf32h(b1);
                blo[nt][0] = tf32h(b0 - __uint_as_float(bhi[nt][0]));
                blo[nt][1] = tf32h(b1 - __uint_as_float(bhi[nt][1]));
            }
            #pragma unroll
            for (int mt = 0; mt < 2; mt++) {
                int ar = warp_m * 32 + mt * 16 + lr;
                float a0 = Xs[ar][kk + lc];
                float a1 = Xs[ar + 8][kk + lc];
                float a2 = Xs[ar][kk + lc + 4];
                float a3 = Xs[ar + 8][kk + lc + 4];
                unsigned ah[4] = {tf32h(a0), tf32h(a1), tf32h(a2), tf32h(a3)};
                unsigned al[4] = {tf32h(a0 - __uint_as_float(ah[0])),
                                  tf32h(a1 - __uint_as_float(ah[1])),
                                  tf32h(a2 - __uint_as_float(ah[2])),
                                  tf32h(a3 - __uint_as_float(ah[3]))};
                #pragma unroll
                for (int nt = 0; nt < 4; nt++) {
                    mma_tf32(acc[mt][nt], al, bhi[nt]);
                    mma_tf32(acc[mt][nt], ah, blo[nt]);
                    mma_tf32(acc[mt][nt], ah, bhi[nt]);
                }
            }
        }
    }

    #pragma unroll
    for (int mt = 0; mt < 2; mt++) {
        #pragma unroll
        for (int nt = 0; nt < 4; nt++) {
            int row = r0 + warp_m * 32 + mt * 16 + lr;
            int colg = n0 + warp_n * 32 + nt * 8 + lc * 2;
            if (row < nrows) {
                float2 v0 = make_float2(acc[mt][nt][0], acc[mt][nt][1]);
                *reinterpret_cast<float2*>(O + (size_t)row * NT + colg) = v0;
            }
            if (row + 8 < nrows) {
                float2 v1 = make_float2(acc[mt][nt][2], acc[mt][nt][3]);
                *reinterpret_cast<float2*>(O + (size_t)(row + 8) * NT + colg) = v1;
            }
        }
    }

    // ---- fused dots epilogue ----
    for (int i = t; i < 128; i += 256) { esr[i] = 0.f; edr[i] = 0.f; }
    __syncthreads();
    float pes[4] = {0, 0, 0, 0}, ped[4] = {0, 0, 0, 0};
    #pragma unroll
    for (int nt = 0; nt < 4; nt++) {
        int cb = warp_n * 32 + nt * 8 + lc * 2;
        float as0 = As[head * 64 + cb], as1 = As[head * 64 + cb + 1];
        float ad0 = Ad[head * 64 + cb], ad1 = Ad[head * 64 + cb + 1];
        #pragma unroll
        for (int mt = 0; mt < 2; mt++) {
            pes[mt * 2 + 0] += acc[mt][nt][0] * as0 + acc[mt][nt][1] * as1;
            pes[mt * 2 + 1] += acc[mt][nt][2] * as0 + acc[mt][nt][3] * as1;
            ped[mt * 2 + 0] += acc[mt][nt][0] * ad0 + acc[mt][nt][1] * ad1;
            ped[mt * 2 + 1] += acc[mt][nt][2] * ad0 + acc[mt][nt][3] * ad1;
        }
    }
    #pragma unroll
    for (int j = 0; j < 4; j++) {
        #pragma unroll
        for (int o = 1; o <= 2; o <<= 1) {
            pes[j] += __shfl_xor_sync(0xffffffffu, pes[j], o);
            ped[j] += __shfl_xor_sync(0xffffffffu, ped[j], o);
        }
    }
    if (lc == 0) {
        #pragma unroll
        for (int j = 0; j < 4; j++) {
            int rl = warp_m * 32 + (j >> 1) * 16 + lr + (j & 1) * 8;
            atomicAdd(&esr[rl], pes[j]);
            atomicAdd(&edr[rl], ped[j]);
        }
    }
    __syncthreads();
    if (t < 128) {
        int row = r0 + t;
        if (row < nrows) {
            esv[(size_t)row * H + head] = esr[t];
            edv[(size_t)row * H + head] = edr[t];
        }
    }
}

// ---------------- attention dot products (layer 1 only) ----------------
template <int H>
__global__ void k_dots(const float* __restrict__ Hm, const float* __restrict__ As,
                       const float* __restrict__ Ad, float* __restrict__ es,
                       float* __restrict__ ed) {
    const int node = blockIdx.x;
    const int w = threadIdx.x >> 5;
    const int l = threadIdx.x & 31;
    const float* hp = Hm + (size_t)node * (H * 64) + w * 64;
    float s1 = fmaf(hp[l], As[w * 64 + l], hp[l + 32] * As[w * 64 + l + 32]);
    float s2 = fmaf(hp[l], Ad[w * 64 + l], hp[l + 32] * Ad[w * 64 + l + 32]);
    #pragma unroll
    for (int o = 16; o; o >>= 1) {
        s1 += __shfl_xor_sync(0xffffffffu, s1, o);
        s2 += __shfl_xor_sync(0xffffffffu, s2, o);
    }
    if (l == 0) { es[node * H + w] = s1; ed[node * H + w] = s2; }
}

// ---------------- warp-per-node fused softmax + aggregation ----------------
// One warp owns one node: no smem, no barriers, online softmax per 32-edge
// chunk, gather with 8-deep per-edge MLP. All control flow is warp-uniform.
template <int H, bool ELU>
__global__ void __launch_bounds__(256)
k_wagg(const float* __restrict__ Hm, const float* __restrict__ es,
       const float* __restrict__ ed, const int* __restrict__ row_ptr,
       const int* __restrict__ col, const float* __restrict__ bias,
       float* __restrict__ out, int n) {
    constexpr int F = H * 64;
    constexpr int R = F / 32;        // regs/thread: 8 (H=4), 2 (H=1)
    const int l = threadIdx.x & 31;
    const int node = blockIdx.x * 8 + (threadIdx.x >> 5);
    if (node >= n) return;

    const int beg = row_ptr[node];
    const int end = row_ptr[node + 1];

    float edv[H];
    if (H == 4) {
        float4 t4 = *reinterpret_cast<const float4*>(ed + (size_t)node * 4);
        edv[0] = t4.x; edv[1] = t4.y; edv[2] = t4.z; edv[3] = t4.w;
    } else {
        edv[0] = ed[node];
    }

    float m[H], den[H], acc[R];
    #pragma unroll
    for (int h = 0; h < H; h++) { m[h] = -FLT_MAX; den[h] = 0.f; }
    #pragma unroll
    for (int j = 0; j < R; j++) acc[j] = 0.f;

    for (int base = beg; base < end; base += 32) {
        const int c = base + l;
        const bool valid = c < end;
        const int s = valid ? col[c] : 0;

        float e[H];
        if (H == 4) {
            float4 t4 = *reinterpret_cast<const float4*>(es + (size_t)s * 4);
            e[0] = t4.x; e[1] = t4.y; e[2] = t4.z; e[3] = t4.w;
        } else {
            e[0] = es[s];
        }

        float a[H], scale[H];
        #pragma unroll
        for (int h = 0; h < H; h++) {
            float v = e[h] + edv[h];
            v = (v > 0.f) ? v : 0.2f * v;
            v = valid ? v : -FLT_MAX;
            float cm = v;
            #pragma unroll
            for (int o = 16; o; o >>= 1) cm = fmaxf(cm, __shfl_xor_sync(0xffffffffu, cm, o));
            float nm = fmaxf(m[h], cm);
            scale[h] = __expf(m[h] - nm);
            m[h] = nm;
            a[h] = valid ? __expf(v - nm) : 0.f;
            float ss = a[h];
            #pragma unroll
            for (int o = 16; o; o >>= 1) ss += __shfl_xor_sync(0xffffffffu, ss, o);
            den[h] = den[h] * scale[h] + ss;
        }
        #pragma unroll
        for (int j = 0; j < R; j++) acc[j] *= scale[(H == 4) ? (j >> 1) : 0];

        const int len = min(32, end - base);
        #pragma unroll 4
        for (int c2 = 0; c2 < len; c2++) {
            const int sc = __shfl_sync(0xffffffffu, s, c2);
            float aa[H];
            #pragma unroll
            for (int h = 0; h < H; h++) aa[h] = __shfl_sync(0xffffffffu, a[h], c2);
            const float* hp = Hm + (size_t)sc * F + l;
            #pragma unroll
            for (int j = 0; j < R; j++)
                acc[j] = fmaf(hp[j * 32], aa[(H == 4) ? (j >> 1) : 0], acc[j]);
        }
    }

    #pragma unroll
    for (int j = 0; j < R; j++) {
        const int h = (H == 4) ? (j >> 1) : 0;
        float res = acc[j] / den[h] + bias[j * 32 + l];
        if (ELU) res = (res > 0.f) ? res : expm1f(res);
        out[(size_t)node * F + j * 32 + l] = res;
    }
}

// ---------------- graph embedding mean ----------------
__global__ void k_zero_f(float* __restrict__ p, int n) {
    int i = blockIdx.x * blockDim.x + threadIdx.x;
    if (i < n) p[i] = 0.f;
}

__global__ void k_mean(const float* __restrict__ node_emb, float* __restrict__ out, int n) {
    const int t = threadIdx.x;  // 64
    float a = 0.f;
    for (int r = blockIdx.x; r < n; r += gridDim.x)
        a += node_emb[(size_t)r * 64 + t];
    atomicAdd(&out[t], a * (1.0f / (float)n));
}

// ---------------- launch ----------------
extern "C" void kernel_launch(void* const* d_in, const int* in_sizes, int n_in,
                              void* d_out, int out_size) {
    const float* x   = (const float*)d_in[0];
    const int*   ei  = (const int*)d_in[1];
    const float* W1  = (const float*)d_in[2];
    const float* a1s = (const float*)d_in[3];
    const float* a1d = (const float*)d_in[4];
    const float* b1  = (const float*)d_in[5];
    const float* W2  = (const float*)d_in[6];
    const float* a2s = (const float*)d_in[7];
    const float* a2d = (const float*)d_in[8];
    const float* b2  = (const float*)d_in[9];
    const float* W3  = (const float*)d_in[10];
    const float* a3s = (const float*)d_in[11];
    const float* a3d = (const float*)d_in[12];
    const float* b3  = (const float*)d_in[13];
    float* out = (float*)d_out;

    const int n = in_sizes[0] / 16;   // 50000
    const int E = in_sizes[1] / 2;    // 800000
    const int tot = E + n;
    const int B = (n + 1023) / 1024;
    const int WB = (n + 7) / 8;       // warp-per-node grid

    float *bufA, *bufB, *es, *ed;
    int *cnt, *cursor, *row_ptr, *col, *part;
    cudaGetSymbolAddress((void**)&bufA, g_bufA);
    cudaGetSymbolAddress((void**)&bufB, g_bufB);
    cudaGetSymbolAddress((void**)&es, g_es);
    cudaGetSymbolAddress((void**)&ed, g_ed);
    cudaGetSymbolAddress((void**)&cnt, g_cnt);
    cudaGetSymbolAddress((void**)&cursor, g_cursor);
    cudaGetSymbolAddress((void**)&row_ptr, g_row_ptr);
    cudaGetSymbolAddress((void**)&col, g_col_src);
    cudaGetSymbolAddress((void**)&part, g_part);

    // CSR by dst
    k_zero_int<<<(n + 255) / 256, 256>>>(cnt, n);
    k_hist<<<(tot + 255) / 256, 256>>>(ei, E, n, cnt);
    k_scan1<<<B, 1024>>>(cnt, n, row_ptr, part);
    k_scan23<<<B, 1024>>>(cnt, n, row_ptr, cursor, part);
    k_scatter<<<(tot + 255) / 256, 256>>>(ei, E, n, cursor, col);

    // layer 1
    k_gemm16<<<(n + 15) / 16, 256>>>(x, W1, bufA, n);
    k_dots<4><<<n, 128>>>(bufA, a1s, a1d, es, ed);
    k_wagg<4, true><<<WB, 256>>>(bufA, es, ed, row_ptr, col, b1, bufB, n);

    // layer 2 (tf32x3 GEMM + fused dots)
    {
        dim3 g((n + 127) / 128, 4);
        k_gemm_tf32<256, 4><<<g, 256>>>(bufB, W2, bufA, n, a2s, a2d, es, ed);
    }
    k_wagg<4, true><<<WB, 256>>>(bufA, es, ed, row_ptr, col, b2, bufB, n);

    // layer 3 (tf32x3 GEMM + fused dots, N=64)
    {
        dim3 g((n + 127) / 128, 1);
        k_gemm_tf32<64, 1><<<g, 256>>>(bufB, W3, bufA, n, a3s, a3d, es, ed);
    }
    k_wagg<1, false><<<WB, 256>>>(bufA, es, ed, row_ptr, col, b3, out, n);

    // graph embedding
    k_zero_f<<<1, 64>>>(out + (size_t)n * 64, 64);
    k_mean<<<256, 64>>>(out, out + (size_t)n * 64, n);
}

// round 8
// speedup vs baseline: 4.0771x; 1.1151x over previous
#include <cuda_runtime.h>
#include <cuda_bf16.h>
#include <float.h>
#include <math.h>

#define NN     50000
#define EEDGE  800000
#define ETOT   (EEDGE + NN)

// ---------------- device scratch ----------------
__device__ float g_bufA[(size_t)NN * 256];
__device__ float g_bufB[(size_t)NN * 256];
__device__ float g_es[(size_t)NN * 4];
__device__ float g_ed[(size_t)NN * 4];
__device__ int   g_cnt[NN];
__device__ int   g_cursor[NN];
__device__ int   g_row_ptr[NN + 1];
__device__ int   g_col_src[ETOT];
__device__ int   g_part[64];

// ---------------- tf32 helpers ----------------
__device__ __forceinline__ unsigned tf32h(float x) {
    unsigned u;
    asm("cvt.rna.tf32.f32 %0, %1;" : "=r"(u) : "f"(x));
    return u;
}
__device__ __forceinline__ void mma_tf32(float* c, const unsigned* a, const unsigned* b) {
    asm volatile("mma.sync.aligned.m16n8k8.row.col.f32.tf32.tf32.f32 "
        "{%0,%1,%2,%3}, {%4,%5,%6,%7}, {%8,%9}, {%0,%1,%2,%3};"
        : "+f"(c[0]), "+f"(c[1]), "+f"(c[2]), "+f"(c[3])
        : "r"(a[0]), "r"(a[1]), "r"(a[2]), "r"(a[3]), "r"(b[0]), "r"(b[1]));
}

// ---------------- CSR construction ----------------
__global__ void k_zero_int(int* __restrict__ p, int n) {
    int i = blockIdx.x * blockDim.x + threadIdx.x;
    if (i < n) p[i] = 0;
}

__global__ void k_hist(const int* __restrict__ ei, int E, int n, int* __restrict__ cnt) {
    int i = blockIdx.x * blockDim.x + threadIdx.x;
    int tot = E + n;
    if (i < tot) {
        int d = (i < E) ? ei[E + i] : (i - E);
        atomicAdd(&cnt[d], 1);
    }
}

__global__ void k_scan1(const int* __restrict__ cnt, int n,
                        int* __restrict__ incl, int* __restrict__ part) {
    __shared__ int sh[1024];
    const int t = threadIdx.x;
    const int i = blockIdx.x * 1024 + t;
    int v = (i < n) ? cnt[i] : 0;
    sh[t] = v;
    __syncthreads();
    #pragma unroll
    for (int o = 1; o < 1024; o <<= 1) {
        int add = (t >= o) ? sh[t - o] : 0;
        __syncthreads();
        sh[t] += add;
        __syncthreads();
    }
    if (i < n) incl[i] = sh[t];
    if (t == 1023) part[blockIdx.x] = sh[1023];
}

__global__ void k_scan23(const int* __restrict__ cnt, int n,
                         int* __restrict__ row_ptr, int* __restrict__ cursor,
                         const int* __restrict__ part) {
    __shared__ int soff;
    const int t = threadIdx.x;
    if (t < 32) {
        int s = 0;
        for (int i = t; i < (int)blockIdx.x; i += 32) s += part[i];
        #pragma unroll
        for (int o = 16; o; o >>= 1) s += __shfl_xor_sync(0xffffffffu, s, o);
        if (t == 0) soff = s;
    }
    __syncthreads();
    const int i = blockIdx.x * 1024 + t;
    if (i < n) {
        int incl = row_ptr[i];
        int c = cnt[i];
        int exc = incl - c + soff;
        row_ptr[i] = exc;
        cursor[i] = exc;
        if (i == n - 1) row_ptr[n] = exc + c;
    }
}

__global__ void k_scatter(const int* __restrict__ ei, int E, int n,
                          int* __restrict__ cursor, int* __restrict__ col_src) {
    int i = blockIdx.x * blockDim.x + threadIdx.x;
    int tot = E + n;
    if (i < tot) {
        int s = (i < E) ? ei[i]     : (i - E);
        int d = (i < E) ? ei[E + i] : (i - E);
        int pos = atomicAdd(&cursor[d], 1);
        col_src[pos] = s;
    }
}

// ---------------- GEMM K=16 (layer 1) + fused attention dots ----------------
__global__ void k_gemm16d(const float* __restrict__ X, const float* __restrict__ W,
                          float* __restrict__ O, int nrows,
                          const float* __restrict__ As, const float* __restrict__ Ad,
                          float* __restrict__ esv, float* __restrict__ edv) {
    __shared__ float Wsh[16 * 256];
    __shared__ float Xsh[16 * 16];
    __shared__ float esr[16][4], edr[16][4];
    const int t = threadIdx.x;
    const int l = t & 31;
    const int head = t >> 6;          // uniform per warp
    const int ci = t & 63;
    for (int i = t; i < 16 * 256; i += 256) Wsh[i] = W[i];
    const int r0 = blockIdx.x * 16;
    {
        int r = t >> 4, c = t & 15;
        int rr = r0 + r; if (rr >= nrows) rr = nrows - 1;
        Xsh[t] = X[(size_t)rr * 16 + c];
    }
    if (t < 64) { esr[t >> 2][t & 3] = 0.f; edr[t >> 2][t & 3] = 0.f; }
    __syncthreads();
    float acc[16];
    #pragma unroll
    for (int r = 0; r < 16; r++) acc[r] = 0.f;
    #pragma unroll
    for (int k = 0; k < 16; k++) {
        float w = Wsh[k * 256 + t];
        #pragma unroll
        for (int r = 0; r < 16; r++) acc[r] = fmaf(Xsh[r * 16 + k], w, acc[r]);
    }
    #pragma unroll
    for (int r = 0; r < 16; r++) {
        int rr = r0 + r;
        if (rr < nrows) O[(size_t)rr * 256 + t] = acc[r];
    }
    // fused dots epilogue
    const float as = As[head * 64 + ci];
    const float ad = Ad[head * 64 + ci];
    #pragma unroll
    for (int r = 0; r < 16; r++) {
        float ps = acc[r] * as;
        float pd = acc[r] * ad;
        #pragma unroll
        for (int o = 16; o; o >>= 1) {
            ps += __shfl_xor_sync(0xffffffffu, ps, o);
            pd += __shfl_xor_sync(0xffffffffu, pd, o);
        }
        if (l == 0) { atomicAdd(&esr[r][head], ps); atomicAdd(&edr[r][head], pd); }
    }
    __syncthreads();
    if (t < 64) {
        int r = t >> 2, hh = t & 3;
        int rr = r0 + r;
        if (rr < nrows) {
            esv[(size_t)rr * 4 + hh] = esr[r][hh];
            edv[(size_t)rr * 4 + hh] = edr[r][hh];
        }
    }
}

// ---------------- tf32x3 tensor GEMM + fused attention dots epilogue ----------------
template <int NT, int H>
__global__ void __launch_bounds__(256)
k_gemm_tf32(const float* __restrict__ X, const float* __restrict__ W,
            float* __restrict__ O, int nrows,
            const float* __restrict__ As, const float* __restrict__ Ad,
            float* __restrict__ esv, float* __restrict__ edv) {
    __shared__ __align__(16) float Xs[128][36];
    __shared__ __align__(16) float Ws[32][72];
    __shared__ float esr[128], edr[128];

    const int t = threadIdx.x;
    const int lane = t & 31;
    const int w = t >> 5;
    const int warp_m = w >> 1;
    const int warp_n = w & 1;
    const int lr = lane >> 2;
    const int lc = lane & 3;
    const int r0 = blockIdx.x * 128;
    const int n0 = blockIdx.y * 64;
    const int head = blockIdx.y;

    float acc[2][4][4];
    #pragma unroll
    for (int mt = 0; mt < 2; mt++)
        #pragma unroll
        for (int nt = 0; nt < 4; nt++)
            #pragma unroll
            for (int i = 0; i < 4; i++) acc[mt][nt][i] = 0.f;

    for (int k0 = 0; k0 < 256; k0 += 32) {
        __syncthreads();
        #pragma unroll
        for (int j = 0; j < 4; j++) {
            int idx = t + j * 256;
            int row = idx >> 3, c4 = idx & 7;
            int rr = r0 + row; if (rr >= nrows) rr = nrows - 1;
            *reinterpret_cast<float4*>(&Xs[row][c4 * 4]) =
                *reinterpret_cast<const float4*>(X + (size_t)rr * 256 + k0 + c4 * 4);
        }
        #pragma unroll
        for (int j = 0; j < 2; j++) {
            int idx = t + j * 256;
            int row = idx >> 4, c4 = idx & 15;
            *reinterpret_cast<float4*>(&Ws[row][c4 * 4]) =
                *reinterpret_cast<const float4*>(W + (size_t)(k0 + row) * NT + n0 + c4 * 4);
        }
        __syncthreads();

        #pragma unroll
        for (int ks = 0; ks < 4; ks++) {
            const int kk = ks * 8;
            unsigned bhi[4][2], blo[4][2];
            #pragma unroll
            for (int nt = 0; nt < 4; nt++) {
                int cb = warp_n * 32 + nt * 8 + lr;
                float b0 = Ws[kk + lc][cb];
                float b1 = Ws[kk + lc + 4][cb];
                bhi[nt][0] = tf32h(b0);
                bhi[nt][1] = tf32h(b1);
                blo[nt][0] = tf32h(b0 - __uint_as_float(bhi[nt][0]));
                blo[nt][1] = tf32h(b1 - __uint_as_float(bhi[nt][1]));
            }
            #pragma unroll
            for (int mt = 0; mt < 2; mt++) {
                int ar = warp_m * 32 + mt * 16 + lr;
                float a0 = Xs[ar][kk + lc];
                float a1 = Xs[ar + 8][kk + lc];
                float a2 = Xs[ar][kk + lc + 4];
                float a3 = Xs[ar + 8][kk + lc + 4];
                unsigned ah[4] = {tf32h(a0), tf32h(a1), tf32h(a2), tf32h(a3)};
                unsigned al[4] = {tf32h(a0 - __uint_as_float(ah[0])),
                                  tf32h(a1 - __uint_as_float(ah[1])),
                                  tf32h(a2 - __uint_as_float(ah[2])),
                                  tf32h(a3 - __uint_as_float(ah[3]))};
                #pragma unroll
                for (int nt = 0; nt < 4; nt++) {
                    mma_tf32(acc[mt][nt], al, bhi[nt]);
                    mma_tf32(acc[mt][nt], ah, blo[nt]);
                    mma_tf32(acc[mt][nt], ah, bhi[nt]);
                }
            }
        }
    }

    #pragma unroll
    for (int mt = 0; mt < 2; mt++) {
        #pragma unroll
        for (int nt = 0; nt < 4; nt++) {
            int row = r0 + warp_m * 32 + mt * 16 + lr;
            int colg = n0 + warp_n * 32 + nt * 8 + lc * 2;
            if (row < nrows) {
                float2 v0 = make_float2(acc[mt][nt][0], acc[mt][nt][1]);
                *reinterpret_cast<float2*>(O + (size_t)row * NT + colg) = v0;
            }
            if (row + 8 < nrows) {
                float2 v1 = make_float2(acc[mt][nt][2], acc[mt][nt][3]);
                *reinterpret_cast<float2*>(O + (size_t)(row + 8) * NT + colg) = v1;
            }
        }
    }

    // ---- fused dots epilogue ----
    for (int i = t; i < 128; i += 256) { esr[i] = 0.f; edr[i] = 0.f; }
    __syncthreads();
    float pes[4] = {0, 0, 0, 0}, ped[4] = {0, 0, 0, 0};
    #pragma unroll
    for (int nt = 0; nt < 4; nt++) {
        int cb = warp_n * 32 + nt * 8 + lc * 2;
        float as0 = As[head * 64 + cb], as1 = As[head * 64 + cb + 1];
        float ad0 = Ad[head * 64 + cb], ad1 = Ad[head * 64 + cb + 1];
        #pragma unroll
        for (int mt = 0; mt < 2; mt++) {
            pes[mt * 2 + 0] += acc[mt][nt][0] * as0 + acc[mt][nt][1] * as1;
            pes[mt * 2 + 1] += acc[mt][nt][2] * as0 + acc[mt][nt][3] * as1;
            ped[mt * 2 + 0] += acc[mt][nt][0] * ad0 + acc[mt][nt][1] * ad1;
            ped[mt * 2 + 1] += acc[mt][nt][2] * ad0 + acc[mt][nt][3] * ad1;
        }
    }
    #pragma unroll
    for (int j = 0; j < 4; j++) {
        #pragma unroll
        for (int o = 1; o <= 2; o <<= 1) {
            pes[j] += __shfl_xor_sync(0xffffffffu, pes[j], o);
            ped[j] += __shfl_xor_sync(0xffffffffu, ped[j], o);
        }
    }
    if (lc == 0) {
        #pragma unroll
        for (int j = 0; j < 4; j++) {
            int rl = warp_m * 32 + (j >> 1) * 16 + lr + (j & 1) * 8;
            atomicAdd(&esr[rl], pes[j]);
            atomicAdd(&edr[rl], ped[j]);
        }
    }
    __syncthreads();
    if (t < 128) {
        int row = r0 + t;
        if (row < nrows) {
            esv[(size_t)row * H + head] = esr[t];
            edv[(size_t)row * H + head] = edr[t];
        }
    }
}

// ---------------- warp-per-node fused softmax + aggregation (vectorized) ----------------
template <int H, bool ELU>
__global__ void __launch_bounds__(256)
k_wagg(const float* __restrict__ Hm, const float* __restrict__ es,
       const float* __restrict__ ed, const int* __restrict__ row_ptr,
       const int* __restrict__ col, const float* __restrict__ bias,
       float* __restrict__ out, int n) {
    constexpr int F = H * 64;
    const int l = threadIdx.x & 31;
    const int node = blockIdx.x * 8 + (threadIdx.x >> 5);
    if (node >= n) return;

    const int beg = row_ptr[node];
    const int end = row_ptr[node + 1];

    float edv[H];
    if (H == 4) {
        float4 t4 = *reinterpret_cast<const float4*>(ed + (size_t)node * 4);
        edv[0] = t4.x; edv[1] = t4.y; edv[2] = t4.z; edv[3] = t4.w;
    } else {
        edv[0] = ed[node];
    }

    float m[H], den[H];
    #pragma unroll
    for (int h = 0; h < H; h++) { m[h] = -FLT_MAX; den[h] = 0.f; }

    // vector accumulators
    float4 acc0 = make_float4(0.f, 0.f, 0.f, 0.f);
    float4 acc1 = make_float4(0.f, 0.f, 0.f, 0.f);
    float2 acc2 = make_float2(0.f, 0.f);
    const int hiLane = l >> 4;   // 0 or 1 (H=4: head select within float4 group)

    for (int base = beg; base < end; base += 32) {
        const int c = base + l;
        const bool valid = c < end;
        const int s = valid ? col[c] : 0;

        float e[H];
        if (H == 4) {
            float4 t4 = *reinterpret_cast<const float4*>(es + (size_t)s * 4);
            e[0] = t4.x; e[1] = t4.y; e[2] = t4.z; e[3] = t4.w;
        } else {
            e[0] = es[s];
        }

        float a[H], scale[H];
        #pragma unroll
        for (int h = 0; h < H; h++) {
            float v = e[h] + edv[h];
            v = (v > 0.f) ? v : 0.2f * v;
            v = valid ? v : -FLT_MAX;
            float cm = v;
            #pragma unroll
            for (int o = 16; o; o >>= 1) cm = fmaxf(cm, __shfl_xor_sync(0xffffffffu, cm, o));
            float nm = fmaxf(m[h], cm);
            scale[h] = __expf(m[h] - nm);
            m[h] = nm;
            a[h] = valid ? __expf(v - nm) : 0.f;
            float ss = a[h];
            #pragma unroll
            for (int o = 16; o; o >>= 1) ss += __shfl_xor_sync(0xffffffffu, ss, o);
            den[h] = den[h] * scale[h] + ss;
        }
        if (H == 4) {
            float s0 = hiLane ? scale[1] : scale[0];
            float s1 = hiLane ? scale[3] : scale[2];
            acc0.x *= s0; acc0.y *= s0; acc0.z *= s0; acc0.w *= s0;
            acc1.x *= s1; acc1.y *= s1; acc1.z *= s1; acc1.w *= s1;
        } else {
            acc2.x *= scale[0]; acc2.y *= scale[0];
        }

        const int len = min(32, end - base);
        #pragma unroll 4
        for (int c2 = 0; c2 < len; c2++) {
            const int sc = __shfl_sync(0xffffffffu, s, c2);
            if (H == 4) {
                float aa[4];
                #pragma unroll
                for (int h = 0; h < 4; h++) aa[h] = __shfl_sync(0xffffffffu, a[h], c2);
                const float a0 = hiLane ? aa[1] : aa[0];
                const float a1 = hiLane ? aa[3] : aa[2];
                const float4* hp = reinterpret_cast<const float4*>(Hm + (size_t)sc * 256);
                float4 v0 = hp[l];
                float4 v1 = hp[l + 32];
                acc0.x = fmaf(v0.x, a0, acc0.x); acc0.y = fmaf(v0.y, a0, acc0.y);
                acc0.z = fmaf(v0.z, a0, acc0.z); acc0.w = fmaf(v0.w, a0, acc0.w);
                acc1.x = fmaf(v1.x, a1, acc1.x); acc1.y = fmaf(v1.y, a1, acc1.y);
                acc1.z = fmaf(v1.z, a1, acc1.z); acc1.w = fmaf(v1.w, a1, acc1.w);
            } else {
                const float aa = __shfl_sync(0xffffffffu, a[0], c2);
                const float2* hp = reinterpret_cast<const float2*>(Hm + (size_t)sc * 64);
                float2 v = hp[l];
                acc2.x = fmaf(v.x, aa, acc2.x);
                acc2.y = fmaf(v.y, aa, acc2.y);
            }
        }
    }

    if (H == 4) {
        const float i0 = 1.0f / (hiLane ? den[1] : den[0]);
        const float i1 = 1.0f / (hiLane ? den[3] : den[2]);
        const float4* bp = reinterpret_cast<const float4*>(bias);
        float4 b0 = bp[l], b1 = bp[l + 32];
        float4 r0, r1;
        r0.x = acc0.x * i0 + b0.x; r0.y = acc0.y * i0 + b0.y;
        r0.z = acc0.z * i0 + b0.z; r0.w = acc0.w * i0 + b0.w;
        r1.x = acc1.x * i1 + b1.x; r1.y = acc1.y * i1 + b1.y;
        r1.z = acc1.z * i1 + b1.z; r1.w = acc1.w * i1 + b1.w;
        if (ELU) {
            r0.x = (r0.x > 0.f) ? r0.x : expm1f(r0.x);
            r0.y = (r0.y > 0.f) ? r0.y : expm1f(r0.y);
            r0.z = (r0.z > 0.f) ? r0.z : expm1f(r0.z);
            r0.w = (r0.w > 0.f) ? r0.w : expm1f(r0.w);
            r1.x = (r1.x > 0.f) ? r1.x : expm1f(r1.x);
            r1.y = (r1.y > 0.f) ? r1.y : expm1f(r1.y);
            r1.z = (r1.z > 0.f) ? r1.z : expm1f(r1.z);
            r1.w = (r1.w > 0.f) ? r1.w : expm1f(r1.w);
        }
        float4* op = reinterpret_cast<float4*>(out + (size_t)node * 256);
        op[l] = r0;
        op[l + 32] = r1;
    } else {
        const float inv = 1.0f / den[0];
        const float2* bp = reinterpret_cast<const float2*>(bias);
        float2 b = bp[l];
        float2 r;
        r.x = acc2.x * inv + b.x;
        r.y = acc2.y * inv + b.y;
        if (ELU) {
            r.x = (r.x > 0.f) ? r.x : expm1f(r.x);
            r.y = (r.y > 0.f) ? r.y : expm1f(r.y);
        }
        reinterpret_cast<float2*>(out + (size_t)node * 64)[l] = r;
    }
}

// ---------------- graph embedding mean ----------------
__global__ void k_zero_f(float* __restrict__ p, int n) {
    int i = blockIdx.x * blockDim.x + threadIdx.x;
    if (i < n) p[i] = 0.f;
}

__global__ void k_mean(const float* __restrict__ node_emb, float* __restrict__ out, int n) {
    const int t = threadIdx.x;  // 64
    float a = 0.f;
    for (int r = blockIdx.x; r < n; r += gridDim.x)
        a += node_emb[(size_t)r * 64 + t];
    atomicAdd(&out[t], a * (1.0f / (float)n));
}

// ---------------- launch ----------------
extern "C" void kernel_launch(void* const* d_in, const int* in_sizes, int n_in,
                              void* d_out, int out_size) {
    const float* x   = (const float*)d_in[0];
    const int*   ei  = (const int*)d_in[1];
    const float* W1  = (const float*)d_in[2];
    const float* a1s = (const float*)d_in[3];
    const float* a1d = (const float*)d_in[4];
    const float* b1  = (const float*)d_in[5];
    const float* W2  = (const float*)d_in[6];
    const float* a2s = (const float*)d_in[7];
    const float* a2d = (const float*)d_in[8];
    const float* b2  = (const float*)d_in[9];
    const float* W3  = (const float*)d_in[10];
    const float* a3s = (const float*)d_in[11];
    const float* a3d = (const float*)d_in[12];
    const float* b3  = (const float*)d_in[13];
    float* out = (float*)d_out;

    const int n = in_sizes[0] / 16;   // 50000
    const int E = in_sizes[1] / 2;    // 800000
    const int tot = E + n;
    const int B = (n + 1023) / 1024;
    const int WB = (n + 7) / 8;

    float *bufA, *bufB, *es, *ed;
    int *cnt, *cursor, *row_ptr, *col, *part;
    cudaGetSymbolAddress((void**)&bufA, g_bufA);
    cudaGetSymbolAddress((void**)&bufB, g_bufB);
    cudaGetSymbolAddress((void**)&es, g_es);
    cudaGetSymbolAddress((void**)&ed, g_ed);
    cudaGetSymbolAddress((void**)&cnt, g_cnt);
    cudaGetSymbolAddress((void**)&cursor, g_cursor);
    cudaGetSymbolAddress((void**)&row_ptr, g_row_ptr);
    cudaGetSymbolAddress((void**)&col, g_col_src);
    cudaGetSymbolAddress((void**)&part, g_part);

    // CSR by dst
    k_zero_int<<<(n + 255) / 256, 256>>>(cnt, n);
    k_hist<<<(tot + 255) / 256, 256>>>(ei, E, n, cnt);
    k_scan1<<<B, 1024>>>(cnt, n, row_ptr, part);
    k_scan23<<<B, 1024>>>(cnt, n, row_ptr, cursor, part);
    k_scatter<<<(tot + 255) / 256, 256>>>(ei, E, n, cursor, col);

    // layer 1 (GEMM + fused dots)
    k_gemm16d<<<(n + 15) / 16, 256>>>(x, W1, bufA, n, a1s, a1d, es, ed);
    k_wagg<4, true><<<WB, 256>>>(bufA, es, ed, row_ptr, col, b1, bufB, n);

    // layer 2 (tf32x3 GEMM + fused dots)
    {
        dim3 g((n + 127) / 128, 4);
        k_gemm_tf32<256, 4><<<g, 256>>>(bufB, W2, bufA, n, a2s, a2d, es, ed);
    }
    k_wagg<4, true><<<WB, 256>>>(bufA, es, ed, row_ptr, col, b2, bufB, n);

    // layer 3 (tf32x3 GEMM + fused dots, N=64)
    {
        dim3 g((n + 127) / 128, 1);
        k_gemm_tf32<64, 1><<<g, 256>>>(bufB, W3, bufA, n, a3s, a3d, es, ed);
    }
    k_wagg<1, false><<<WB, 256>>>(bufA, es, ed, row_ptr, col, b3, out, n);

    // graph embedding
    k_zero_f<<<1, 64>>>(out + (size_t)n * 64, 64);
    k_mean<<<256, 64>>>(out, out + (size_t)n * 64, n);
}